// round 12
// baseline (speedup 1.0000x reference)
#include <cuda_runtime.h>
#include <cuda_fp16.h>
#include <cstdint>

#define D 128
#define MAXN 100096
#define EMAX 1700000
#define SPU 132

__device__ __half g_hs [MAXN * D];    // fp16 features (scaled by dis after k_scale)
__device__ __half g_buf[MAXN * D];    // fp16 layer output -> next layer input
__device__ uint2  g_wsp[3][64 * 128]; // pre-split W: {hi2, lo2} per (k2, col)
__device__ int    g_deg[MAXN];
__device__ int    g_indeg[MAXN];
__device__ int    g_off[MAXN + 1];
__device__ int    g_pos[MAXN];
__device__ int    g_csr[EMAX];
__device__ float  g_dis[MAXN];
__device__ int    g_is64;

__device__ __forceinline__ uint32_t packh2(float a, float b) {
    __half2 h = __floats2half2_rn(a, b);
    return *reinterpret_cast<uint32_t*>(&h);
}

__device__ __forceinline__ uint32_t hadd2u(uint32_t a, uint32_t b) {
    __half2 r = __hadd2(*reinterpret_cast<__half2*>(&a),
                        *reinterpret_cast<__half2*>(&b));
    return *reinterpret_cast<uint32_t*>(&r);
}

// --------------------------------------------------------------------------
__global__ void k_pre(const int* __restrict__ e32, int n,
                      const float* __restrict__ W1,
                      const float* __restrict__ W2,
                      const float* __restrict__ W3) {
    int i = blockIdx.x * blockDim.x + threadIdx.x;
    if (i == 0) {
        int nz = 0;
        #pragma unroll 1
        for (int q = 0; q < 64; q++) nz += (e32[2 * q + 1] != 0);
        g_is64 = (nz == 0) ? 1 : 0;
    }
    if (i < n) { g_deg[i] = 1; g_indeg[i] = 0; }
    if (i < 3 * 8192) {
        const int l   = i >> 13;
        const int rem = i & 8191;
        const int k2  = rem >> 7;
        const int col = rem & 127;
        const float* W = (l == 0) ? W1 : (l == 1) ? W2 : W3;
        float w0 = W[col * 128 + 2 * k2];
        float w1 = W[col * 128 + 2 * k2 + 1];
        float h0f = __half2float(__float2half_rn(w0));
        float h1f = __half2float(__float2half_rn(w1));
        g_wsp[l][k2 * 128 + col] =
            make_uint2(packh2(w0, w1), packh2(w0 - h0f, w1 - h1f));
    }
}

__global__ void k_count(const void* __restrict__ ep, long long E) {
    long long e = (long long)blockIdx.x * blockDim.x + threadIdx.x;
    if (e >= E) return;
    int r, c;
    if (g_is64) {
        const long long* p = (const long long*)ep;
        r = (int)p[e]; c = (int)p[e + E];
    } else {
        const int* p = (const int*)ep;
        r = p[e]; c = p[e + E];
    }
    atomicAdd(&g_deg[r], 1);
    atomicAdd(&g_indeg[c], 1);
}

__global__ void k_dis(int n) {
    int i = blockIdx.x * blockDim.x + threadIdx.x;
    if (i < n) g_dis[i] = rsqrtf((float)g_deg[i]);
}

__global__ __launch_bounds__(1024) void k_scan(int n) {
    __shared__ int s[1024];
    const int t = threadIdx.x;
    const int chunk = (n + 1023) / 1024;
    const int start = t * chunk;
    const int end = min(start + chunk, n);
    int sum = 0;
    for (int i = start; i < end; i++) sum += g_indeg[i];
    s[t] = sum;
    __syncthreads();
    for (int o = 1; o < 1024; o <<= 1) {
        int v = (t >= o) ? s[t - o] : 0;
        __syncthreads();
        s[t] += v;
        __syncthreads();
    }
    int run = (t == 0) ? 0 : s[t - 1];
    for (int i = start; i < end; i++) {
        g_off[i] = run;
        g_pos[i] = run;
        run += g_indeg[i];
    }
    if (t == 1023) g_off[n] = s[1023];
}

__global__ void k_fill(const void* __restrict__ ep, long long E) {
    long long e = (long long)blockIdx.x * blockDim.x + threadIdx.x;
    if (e >= E) return;
    int r, c;
    if (g_is64) {
        const long long* p = (const long long*)ep;
        r = (int)p[e]; c = (int)p[e + E];
    } else {
        const int* p = (const int*)ep;
        r = p[e]; c = p[e + E];
    }
    int p = atomicAdd(&g_pos[c], 1);
    g_csr[p] = r;
}

// scale hs by dis (row-wise), one thread per uint4 (8 halves)
__global__ void k_scale(int n) {
    long long t = (long long)blockIdx.x * blockDim.x + threadIdx.x;
    if (t >= (long long)n * 16) return;
    const int node = (int)(t >> 4);
    __half2 d2 = __float2half2_rn(g_dis[node]);
    uint4 v = ((const uint4*)g_hs)[t];
    __half2* h = reinterpret_cast<__half2*>(&v);
    h[0] = __hmul2(h[0], d2);
    h[1] = __hmul2(h[1], d2);
    h[2] = __hmul2(h[2], d2);
    h[3] = __hmul2(h[3], d2);
    ((uint4*)g_hs)[t] = v;
}

// --------------------------------------------------------------------------
__device__ __forceinline__ void mma_f16(float c[4],
                                        uint32_t a0, uint32_t a1, uint32_t a2, uint32_t a3,
                                        uint32_t b0, uint32_t b1) {
    asm volatile(
        "mma.sync.aligned.m16n8k16.row.col.f32.f16.f16.f32 "
        "{%0,%1,%2,%3}, {%4,%5,%6,%7}, {%8,%9}, {%0,%1,%2,%3};"
        : "+f"(c[0]), "+f"(c[1]), "+f"(c[2]), "+f"(c[3])
        : "r"(a0), "r"(a1), "r"(a2), "r"(a3), "r"(b0), "r"(b1));
}

// layer-1 GEMM: fp32 X, hi/lo split; NO dis in epilogue (k_scale applies it)
__global__ __launch_bounds__(256, 2) void k_gemm1(const float* __restrict__ X,
                                                  const uint2* __restrict__ Wsp,
                                                  const float* __restrict__ Bv,
                                                  int n) {
    __shared__ uint2 sA[2][8][SPU];
    __shared__ uint2 sB[2][8][SPU];

    const int tid  = threadIdx.x;
    const int lane = tid & 31;
    const int wid  = tid >> 5;
    const int warpRow = wid >> 1;
    const int warpCol = wid & 1;
    const int row0 = blockIdx.x * 128;
    const int lr = lane >> 2;
    const int lq = lane & 3;

    const int xr0 = tid >> 2;
    const int xq0 = (tid & 3) * 4;
    const int xr1 = (256 + tid) >> 2;
    const int xq1 = ((256 + tid) & 3) * 4;
    const int wk0 = tid >> 7, wc0 = tid & 127;

    float4 xv0, xv1;
    uint2  wv[4];

    #define G1_LOAD(K0)                                                          \
        do {                                                                     \
            int gr0 = row0 + xr0, gr1 = row0 + xr1;                              \
            xv0 = (gr0 < n) ? *(const float4*)&X[(long long)gr0 * 128 + (K0) + xq0] \
                            : make_float4(0.f, 0.f, 0.f, 0.f);                   \
            xv1 = (gr1 < n) ? *(const float4*)&X[(long long)gr1 * 128 + (K0) + xq1] \
                            : make_float4(0.f, 0.f, 0.f, 0.f);                   \
            const int k02 = (K0) >> 1;                                           \
            wv[0] = Wsp[(k02 + wk0 + 0) * 128 + wc0];                            \
            wv[1] = Wsp[(k02 + wk0 + 2) * 128 + wc0];                            \
            wv[2] = Wsp[(k02 + wk0 + 4) * 128 + wc0];                            \
            wv[3] = Wsp[(k02 + wk0 + 6) * 128 + wc0];                            \
        } while (0)

    #define G1_STORE(B)                                                          \
        do {                                                                     \
            float xe0[4] = {xv0.x, xv0.y, xv0.z, xv0.w};                         \
            float xe1[4] = {xv1.x, xv1.y, xv1.z, xv1.w};                         \
            float xl0[4], xl1[4];                                                \
            _Pragma("unroll")                                                    \
            for (int q = 0; q < 4; q++) {                                        \
                xl0[q] = xe0[q] - __half2float(__float2half_rn(xe0[q]));         \
                xl1[q] = xe1[q] - __half2float(__float2half_rn(xe1[q]));         \
            }                                                                    \
            sA[B][(xq0 >> 1) + 0][xr0] = make_uint2(packh2(xe0[0], xe0[1]), packh2(xl0[0], xl0[1])); \
            sA[B][(xq0 >> 1) + 1][xr0] = make_uint2(packh2(xe0[2], xe0[3]), packh2(xl0[2], xl0[3])); \
            sA[B][(xq1 >> 1) + 0][xr1] = make_uint2(packh2(xe1[0], xe1[1]), packh2(xl1[0], xl1[1])); \
            sA[B][(xq1 >> 1) + 1][xr1] = make_uint2(packh2(xe1[2], xe1[3]), packh2(xl1[2], xl1[3])); \
            sB[B][wk0 + 0][wc0] = wv[0];                                         \
            sB[B][wk0 + 2][wc0] = wv[1];                                         \
            sB[B][wk0 + 4][wc0] = wv[2];                                         \
            sB[B][wk0 + 6][wc0] = wv[3];                                         \
        } while (0)

    float c[2][8][4];
    #pragma unroll
    for (int mt = 0; mt < 2; mt++)
        #pragma unroll
        for (int nt = 0; nt < 8; nt++)
            #pragma unroll
            for (int q = 0; q < 4; q++) c[mt][nt][q] = 0.f;

    G1_LOAD(0);
    G1_STORE(0);
    __syncthreads();

    #pragma unroll
    for (int t = 0; t < 8; t++) {
        const int b = t & 1;
        if (t < 7) G1_LOAD((t + 1) * 16);

        uint32_t ahi[2][4], alo[2][4];
        #pragma unroll
        for (int mt = 0; mt < 2; mt++) {
            int r = warpRow * 32 + mt * 16 + lr;
            #pragma unroll
            for (int kg = 0; kg < 2; kg++) {
                uint2 v0 = sA[b][kg * 4 + lq][r];
                uint2 v1 = sA[b][kg * 4 + lq][r + 8];
                ahi[mt][kg * 2 + 0] = v0.x; alo[mt][kg * 2 + 0] = v0.y;
                ahi[mt][kg * 2 + 1] = v1.x; alo[mt][kg * 2 + 1] = v1.y;
            }
        }
        #pragma unroll
        for (int nt = 0; nt < 8; nt++) {
            int col = warpCol * 64 + nt * 8 + lr;
            uint2 w0 = sB[b][0 * 4 + lq][col];
            uint2 w1 = sB[b][1 * 4 + lq][col];
            #pragma unroll
            for (int mt = 0; mt < 2; mt++) {
                mma_f16(c[mt][nt], ahi[mt][0], ahi[mt][1], ahi[mt][2], ahi[mt][3], w0.x, w1.x);
                mma_f16(c[mt][nt], ahi[mt][0], ahi[mt][1], ahi[mt][2], ahi[mt][3], w0.y, w1.y);
                mma_f16(c[mt][nt], alo[mt][0], alo[mt][1], alo[mt][2], alo[mt][3], w0.x, w1.x);
            }
        }
        if (t < 7) G1_STORE(b ^ 1);
        __syncthreads();
    }

    #pragma unroll
    for (int mt = 0; mt < 2; mt++) {
        #pragma unroll
        for (int h2 = 0; h2 < 2; h2++) {
            int gi = row0 + warpRow * 32 + mt * 16 + lr + h2 * 8;
            if (gi >= n) continue;
            #pragma unroll
            for (int nt = 0; nt < 8; nt++) {
                int col = warpCol * 64 + nt * 8 + lq * 2;
                float ox = c[mt][nt][h2 * 2 + 0] + Bv[col];
                float oy = c[mt][nt][h2 * 2 + 1] + Bv[col + 1];
                *(__half2*)&g_hs[(long long)gi * 128 + col] = __floats2half2_rn(ox, oy);
            }
        }
    }
}

// layers 2-3 GEMM: X exact fp16; dis in epilogue (available by then)
__global__ __launch_bounds__(256, 2) void k_gemm2(const uint2* __restrict__ Wsp,
                                                  const float* __restrict__ Bv,
                                                  int n) {
    __shared__ uint32_t sA[2][8][SPU];
    __shared__ uint2    sB[2][8][SPU];

    const int tid  = threadIdx.x;
    const int lane = tid & 31;
    const int wid  = tid >> 5;
    const int warpRow = wid >> 1;
    const int warpCol = wid & 1;
    const int row0 = blockIdx.x * 128;
    const int lr = lane >> 2;
    const int lq = lane & 3;

    const int xr0 = tid >> 2;
    const int xq0 = (tid & 3) * 4;
    const int xr1 = (256 + tid) >> 2;
    const int xq1 = ((256 + tid) & 3) * 4;
    const int wk0 = tid >> 7, wc0 = tid & 127;

    uint2 xv0, xv1;
    uint2 wv[4];

    #define G2_LOAD(K0)                                                          \
        do {                                                                     \
            int gr0 = row0 + xr0, gr1 = row0 + xr1;                              \
            xv0 = (gr0 < n) ? *(const uint2*)&g_buf[(long long)gr0 * 128 + (K0) + xq0] \
                            : make_uint2(0u, 0u);                                \
            xv1 = (gr1 < n) ? *(const uint2*)&g_buf[(long long)gr1 * 128 + (K0) + xq1] \
                            : make_uint2(0u, 0u);                                \
            const int k02 = (K0) >> 1;                                           \
            wv[0] = Wsp[(k02 + wk0 + 0) * 128 + wc0];                            \
            wv[1] = Wsp[(k02 + wk0 + 2) * 128 + wc0];                            \
            wv[2] = Wsp[(k02 + wk0 + 4) * 128 + wc0];                            \
            wv[3] = Wsp[(k02 + wk0 + 6) * 128 + wc0];                            \
        } while (0)

    #define G2_STORE(B)                                                          \
        do {                                                                     \
            sA[B][(xq0 >> 1) + 0][xr0] = xv0.x;                                  \
            sA[B][(xq0 >> 1) + 1][xr0] = xv0.y;                                  \
            sA[B][(xq1 >> 1) + 0][xr1] = xv1.x;                                  \
            sA[B][(xq1 >> 1) + 1][xr1] = xv1.y;                                  \
            sB[B][wk0 + 0][wc0] = wv[0];                                         \
            sB[B][wk0 + 2][wc0] = wv[1];                                         \
            sB[B][wk0 + 4][wc0] = wv[2];                                         \
            sB[B][wk0 + 6][wc0] = wv[3];                                         \
        } while (0)

    float c[2][8][4];
    #pragma unroll
    for (int mt = 0; mt < 2; mt++)
        #pragma unroll
        for (int nt = 0; nt < 8; nt++)
            #pragma unroll
            for (int q = 0; q < 4; q++) c[mt][nt][q] = 0.f;

    G2_LOAD(0);
    G2_STORE(0);
    __syncthreads();

    #pragma unroll
    for (int t = 0; t < 8; t++) {
        const int b = t & 1;
        if (t < 7) G2_LOAD((t + 1) * 16);

        uint32_t a[2][4];
        #pragma unroll
        for (int mt = 0; mt < 2; mt++) {
            int r = warpRow * 32 + mt * 16 + lr;
            #pragma unroll
            for (int kg = 0; kg < 2; kg++) {
                a[mt][kg * 2 + 0] = sA[b][kg * 4 + lq][r];
                a[mt][kg * 2 + 1] = sA[b][kg * 4 + lq][r + 8];
            }
        }
        #pragma unroll
        for (int nt = 0; nt < 8; nt++) {
            int col = warpCol * 64 + nt * 8 + lr;
            uint2 w0 = sB[b][0 * 4 + lq][col];
            uint2 w1 = sB[b][1 * 4 + lq][col];
            #pragma unroll
            for (int mt = 0; mt < 2; mt++) {
                mma_f16(c[mt][nt], a[mt][0], a[mt][1], a[mt][2], a[mt][3], w0.x, w1.x);
                mma_f16(c[mt][nt], a[mt][0], a[mt][1], a[mt][2], a[mt][3], w0.y, w1.y);
            }
        }
        if (t < 7) G2_STORE(b ^ 1);
        __syncthreads();
    }

    #pragma unroll
    for (int mt = 0; mt < 2; mt++) {
        #pragma unroll
        for (int h2 = 0; h2 < 2; h2++) {
            int gi = row0 + warpRow * 32 + mt * 16 + lr + h2 * 8;
            if (gi >= n) continue;
            float dv = g_dis[gi];
            #pragma unroll
            for (int nt = 0; nt < 8; nt++) {
                int col = warpCol * 64 + nt * 8 + lq * 2;
                float ox = dv * (c[mt][nt][h2 * 2 + 0] + Bv[col]);
                float oy = dv * (c[mt][nt][h2 * 2 + 1] + Bv[col + 1]);
                *(__half2*)&g_hs[(long long)gi * 128 + col] = __floats2half2_rn(ox, oy);
            }
        }
    }
}

// --------------------------------------------------------------------------
// Pull aggregation v6: half-warp per node; 8/4/2/1 batched fp16 trees.
// --------------------------------------------------------------------------
#define CONVACC(u)                                                               \
    do {                                                                         \
        float2 f;                                                                \
        f = __half22float2(*reinterpret_cast<__half2*>(&(u).x)); a0 += f.x; a1 += f.y; \
        f = __half22float2(*reinterpret_cast<__half2*>(&(u).y)); a2 += f.x; a3 += f.y; \
        f = __half22float2(*reinterpret_cast<__half2*>(&(u).z)); a4 += f.x; a5 += f.y; \
        f = __half22float2(*reinterpret_cast<__half2*>(&(u).w)); a6 += f.x; a7 += f.y; \
    } while (0)

__global__ __launch_bounds__(256) void k_agg(float* __restrict__ dst,
                                             int to_buf, int n) {
    const int node = (blockIdx.x * 256 + threadIdx.x) >> 4;
    if (node >= n) return;
    const int sl = threadIdx.x & 15;

    const int beg = g_off[node];
    const int end = g_off[node + 1];

    const uint4* hsb = (const uint4*)g_hs;

    float a0, a1, a2, a3, a4, a5, a6, a7;
    {   // self-loop row
        uint4 v = hsb[(long long)node * 16 + sl];
        float2 f;
        f = __half22float2(*reinterpret_cast<__half2*>(&v.x)); a0 = f.x; a1 = f.y;
        f = __half22float2(*reinterpret_cast<__half2*>(&v.y)); a2 = f.x; a3 = f.y;
        f = __half22float2(*reinterpret_cast<__half2*>(&v.z)); a4 = f.x; a5 = f.y;
        f = __half22float2(*reinterpret_cast<__half2*>(&v.w)); a6 = f.x; a7 = f.y;
    }

    int j = beg;
    for (; j + 8 <= end; j += 8) {
        int i0 = __ldg(&g_csr[j + 0]);
        int i1 = __ldg(&g_csr[j + 1]);
        int i2 = __ldg(&g_csr[j + 2]);
        int i3 = __ldg(&g_csr[j + 3]);
        int i4 = __ldg(&g_csr[j + 4]);
        int i5 = __ldg(&g_csr[j + 5]);
        int i6 = __ldg(&g_csr[j + 6]);
        int i7 = __ldg(&g_csr[j + 7]);
        uint4 v0 = __ldg(&hsb[(long long)i0 * 16 + sl]);
        uint4 v1 = __ldg(&hsb[(long long)i1 * 16 + sl]);
        uint4 v2 = __ldg(&hsb[(long long)i2 * 16 + sl]);
        uint4 v3 = __ldg(&hsb[(long long)i3 * 16 + sl]);
        uint4 v4 = __ldg(&hsb[(long long)i4 * 16 + sl]);
        uint4 v5 = __ldg(&hsb[(long long)i5 * 16 + sl]);
        uint4 v6 = __ldg(&hsb[(long long)i6 * 16 + sl]);
        uint4 v7 = __ldg(&hsb[(long long)i7 * 16 + sl]);
        uint4 sA4, sB4;
        sA4.x = hadd2u(hadd2u(v0.x, v1.x), hadd2u(v2.x, v3.x));
        sA4.y = hadd2u(hadd2u(v0.y, v1.y), hadd2u(v2.y, v3.y));
        sA4.z = hadd2u(hadd2u(v0.z, v1.z), hadd2u(v2.z, v3.z));
        sA4.w = hadd2u(hadd2u(v0.w, v1.w), hadd2u(v2.w, v3.w));
        sB4.x = hadd2u(hadd2u(v4.x, v5.x), hadd2u(v6.x, v7.x));
        sB4.y = hadd2u(hadd2u(v4.y, v5.y), hadd2u(v6.y, v7.y));
        sB4.z = hadd2u(hadd2u(v4.z, v5.z), hadd2u(v6.z, v7.z));
        sB4.w = hadd2u(hadd2u(v4.w, v5.w), hadd2u(v6.w, v7.w));
        CONVACC(sA4);
        CONVACC(sB4);
    }
    if (j + 4 <= end) {
        int i0 = __ldg(&g_csr[j + 0]);
        int i1 = __ldg(&g_csr[j + 1]);
        int i2 = __ldg(&g_csr[j + 2]);
        int i3 = __ldg(&g_csr[j + 3]);
        uint4 v0 = __ldg(&hsb[(long long)i0 * 16 + sl]);
        uint4 v1 = __ldg(&hsb[(long long)i1 * 16 + sl]);
        uint4 v2 = __ldg(&hsb[(long long)i2 * 16 + sl]);
        uint4 v3 = __ldg(&hsb[(long long)i3 * 16 + sl]);
        uint4 s4;
        s4.x = hadd2u(hadd2u(v0.x, v1.x), hadd2u(v2.x, v3.x));
        s4.y = hadd2u(hadd2u(v0.y, v1.y), hadd2u(v2.y, v3.y));
        s4.z = hadd2u(hadd2u(v0.z, v1.z), hadd2u(v2.z, v3.z));
        s4.w = hadd2u(hadd2u(v0.w, v1.w), hadd2u(v2.w, v3.w));
        CONVACC(s4);
        j += 4;
    }
    if (j + 2 <= end) {
        int i0 = __ldg(&g_csr[j + 0]);
        int i1 = __ldg(&g_csr[j + 1]);
        uint4 v0 = __ldg(&hsb[(long long)i0 * 16 + sl]);
        uint4 v1 = __ldg(&hsb[(long long)i1 * 16 + sl]);
        uint4 s2;
        s2.x = hadd2u(v0.x, v1.x);
        s2.y = hadd2u(v0.y, v1.y);
        s2.z = hadd2u(v0.z, v1.z);
        s2.w = hadd2u(v0.w, v1.w);
        CONVACC(s2);
        j += 2;
    }
    if (j < end) {
        int i0 = __ldg(&g_csr[j]);
        uint4 v0 = __ldg(&hsb[(long long)i0 * 16 + sl]);
        CONVACC(v0);
    }

    const float dv = g_dis[node];
    a0 = fmaxf(dv * a0, 0.f); a1 = fmaxf(dv * a1, 0.f);
    a2 = fmaxf(dv * a2, 0.f); a3 = fmaxf(dv * a3, 0.f);
    a4 = fmaxf(dv * a4, 0.f); a5 = fmaxf(dv * a5, 0.f);
    a6 = fmaxf(dv * a6, 0.f); a7 = fmaxf(dv * a7, 0.f);

    if (to_buf) {
        uint4 o;
        o.x = packh2(a0, a1); o.y = packh2(a2, a3);
        o.z = packh2(a4, a5); o.w = packh2(a6, a7);
        ((uint4*)g_buf)[(long long)node * 16 + sl] = o;
    } else {
        float4* op = (float4*)&dst[((long long)node << 7) + sl * 8];
        op[0] = make_float4(a0, a1, a2, a3);
        op[1] = make_float4(a4, a5, a6, a7);
    }
}

// --------------------------------------------------------------------------
extern "C" void kernel_launch(void* const* d_in, const int* in_sizes, int n_in,
                              void* d_out, int out_size) {
    const float* x  = (const float*)d_in[0];
    const void*  ep = d_in[1];
    const float* W1 = (const float*)d_in[2];
    const float* b1 = (const float*)d_in[3];
    const float* W2 = (const float*)d_in[4];
    const float* b2 = (const float*)d_in[5];
    const float* W3 = (const float*)d_in[6];
    const float* b3 = (const float*)d_in[7];
    float* out = (float*)d_out;

    const int n = in_sizes[0] / D;
    const long long E = (long long)in_sizes[1] / 2;

    const int tb = 256;
    const int nb_n    = (n + tb - 1) / tb;
    const int nb_e    = (int)((E + tb - 1) / tb);
    const int nb_gemm = (n + 127) / 128;
    const int nb_agg  = (n + 15) / 16;
    const int nb_sc   = (int)(((long long)n * 16 + tb - 1) / tb);

    uint2* wsp;
    cudaGetSymbolAddress((void**)&wsp, g_wsp);

    static cudaStream_t s2 = nullptr;
    static cudaEvent_t evP = nullptr, evD = nullptr, evF = nullptr;
    if (s2 == nullptr) {
        cudaStreamCreateWithFlags(&s2, cudaStreamNonBlocking);
        cudaEventCreateWithFlags(&evP, cudaEventDisableTiming);
        cudaEventCreateWithFlags(&evD, cudaEventDisableTiming);
        cudaEventCreateWithFlags(&evF, cudaEventDisableTiming);
    }

    // main: W-split + init
    k_pre<<<nb_n, tb>>>((const int*)ep, n, W1, W2, W3);
    cudaEventRecord(evP, 0);

    // side: full graph preprocessing (count -> dis -> scan -> fill)
    cudaStreamWaitEvent(s2, evP, 0);
    k_count<<<nb_e, tb, 0, s2>>>(ep, E);
    k_dis<<<nb_n, tb, 0, s2>>>(n);
    cudaEventRecord(evD, s2);
    k_scan<<<1, 1024, 0, s2>>>(n);
    k_fill<<<nb_e, tb, 0, s2>>>(ep, E);
    cudaEventRecord(evF, s2);

    // main: layer-1 GEMM overlaps the whole graph build
    k_gemm1<<<nb_gemm, 256>>>(x, wsp, b1, n);
    cudaStreamWaitEvent(0, evD, 0);
    k_scale<<<nb_sc, tb>>>(n);

    cudaStreamWaitEvent(0, evF, 0);
    k_agg<<<nb_agg, 256>>>(out, 1, n);
    k_gemm2<<<nb_gemm, 256>>>(wsp + 8192, b2, n);
    k_agg<<<nb_agg, 256>>>(out, 1, n);
    k_gemm2<<<nb_gemm, 256>>>(wsp + 2 * 8192, b3, n);
    k_agg<<<nb_agg, 256>>>(out, 0, n);
}